// round 1
// baseline (speedup 1.0000x reference)
#include <cuda_runtime.h>
#include <cuda_bf16.h>
#include <cstdint>

// ---------------------------------------------------------------------------
// Problem sizes (fixed)
// ---------------------------------------------------------------------------
#define BB 8
#define QQ 128
#define VV 512
#define HH 512

// ---------------------------------------------------------------------------
// Device scratch (no allocations allowed)
// ---------------------------------------------------------------------------
__device__ __nv_bfloat16 g_qhi[BB*QQ*HH], g_qlo[BB*QQ*HH];
__device__ __nv_bfloat16 g_vhi[BB*VV*HH], g_vlo[BB*VV*HH];
__device__ __nv_bfloat16 g_wqhi[HH*HH], g_wqlo[HH*HH];
__device__ __nv_bfloat16 g_wvhi[HH*HH], g_wvlo[HH*HH];
__device__ float g_qp[BB*QQ*HH];
__device__ float g_vp[BB*VV*HH];

// ---------------------------------------------------------------------------
// Fast-but-accurate transcendentals (always MUFU, regardless of compile flags)
// ---------------------------------------------------------------------------
__device__ __forceinline__ float fast_ex2(float x) {
    float y;
    asm("ex2.approx.ftz.f32 %0, %1;" : "=f"(y) : "f"(x));
    return y;
}
__device__ __forceinline__ float fast_rcp(float x) {
    float y;
    asm("rcp.approx.ftz.f32 %0, %1;" : "=f"(y) : "f"(x));
    return y;
}
// tanh(x) = 1 - 2/(1+e^{2x});  abs err ~1e-6, 2 MUFU + 3 FMA-pipe ops
__device__ __forceinline__ float tanh_acc(float x) {
    float e = fast_ex2(x * 2.8853900817779268f);   // e^{2x}
    return fmaf(-2.0f, fast_rcp(1.0f + e), 1.0f);
}

// ---------------------------------------------------------------------------
// K1: split fp32 -> bf16 hi + bf16 lo
// ---------------------------------------------------------------------------
__global__ void convert_split_kernel(const float* __restrict__ src,
                                     __nv_bfloat16* __restrict__ hi,
                                     __nv_bfloat16* __restrict__ lo, int n) {
    int i = blockIdx.x * blockDim.x + threadIdx.x;
    if (i < n) {
        float x = src[i];
        __nv_bfloat16 h = __float2bfloat16(x);
        float r = x - __bfloat162float(h);
        hi[i] = h;
        lo[i] = __float2bfloat16(r);
    }
}

// ---------------------------------------------------------------------------
// K2: C[m][n] = sum_k A[m][k]*B[n][k] + bias[n]   (NT GEMM, 3x bf16 split)
// Block tile 128x64, BK=32, 8 warps (4x2), warp tile 32x32 via m16n8k16.
// ---------------------------------------------------------------------------
#define GBM 128
#define GBN 64
#define GBK 32

__device__ __forceinline__ void mma16816(float* d, const uint32_t* a, const uint32_t* b) {
    asm volatile(
        "mma.sync.aligned.m16n8k16.row.col.f32.bf16.bf16.f32 "
        "{%0,%1,%2,%3}, {%4,%5,%6,%7}, {%8,%9}, {%0,%1,%2,%3};"
        : "+f"(d[0]), "+f"(d[1]), "+f"(d[2]), "+f"(d[3])
        : "r"(a[0]), "r"(a[1]), "r"(a[2]), "r"(a[3]), "r"(b[0]), "r"(b[1]));
}

__global__ __launch_bounds__(256) void gemm_nt_split_kernel(
    const __nv_bfloat16* __restrict__ Ahi, const __nv_bfloat16* __restrict__ Alo,
    const __nv_bfloat16* __restrict__ Bhi, const __nv_bfloat16* __restrict__ Blo,
    const float* __restrict__ bias, float* __restrict__ C) {
    const int K = HH;  // 512
    const int N = HH;  // 512
    __shared__ __align__(16) __nv_bfloat16 As[2][GBM][GBK + 8];
    __shared__ __align__(16) __nv_bfloat16 Bs[2][GBN][GBK + 8];

    const int m0 = blockIdx.x * GBM;
    const int n0 = blockIdx.y * GBN;
    const int tid = threadIdx.x;
    const int wid = tid >> 5;
    const int lane = tid & 31;
    const int wm = (wid >> 1) * 32;  // warp m offset in block tile
    const int wn = (wid & 1) * 32;   // warp n offset
    const int gp = lane >> 2;
    const int tg = lane & 3;

    float d[2][4][4];
#pragma unroll
    for (int mi = 0; mi < 2; mi++)
#pragma unroll
        for (int ni = 0; ni < 4; ni++)
#pragma unroll
            for (int r = 0; r < 4; r++) d[mi][ni][r] = 0.0f;

    for (int k0 = 0; k0 < K; k0 += GBK) {
        __syncthreads();
        // stage A (128x32) hi+lo and B (64x32) hi+lo
#pragma unroll
        for (int s = 0; s < 2; s++) {
            const __nv_bfloat16* srcA = s ? Alo : Ahi;
#pragma unroll
            for (int i = 0; i < 2; i++) {
                int linear = i * 256 + tid;
                int r = linear >> 2;
                int c = (linear & 3) * 8;
                uint4 v = *(const uint4*)(srcA + (size_t)(m0 + r) * K + k0 + c);
                *(uint4*)(&As[s][r][c]) = v;
            }
            const __nv_bfloat16* srcB = s ? Blo : Bhi;
            {
                int r = tid >> 2;
                int c = (tid & 3) * 8;
                uint4 v = *(const uint4*)(srcB + (size_t)(n0 + r) * K + k0 + c);
                *(uint4*)(&Bs[s][r][c]) = v;
            }
        }
        __syncthreads();

#pragma unroll
        for (int ks = 0; ks < GBK; ks += 16) {
            uint32_t a[2][2][4];
            uint32_t bf[2][4][2];
#pragma unroll
            for (int s = 0; s < 2; s++) {
#pragma unroll
                for (int mi = 0; mi < 2; mi++) {
                    int row = wm + mi * 16;
                    a[s][mi][0] = *(const uint32_t*)&As[s][row + gp][ks + tg * 2];
                    a[s][mi][1] = *(const uint32_t*)&As[s][row + gp + 8][ks + tg * 2];
                    a[s][mi][2] = *(const uint32_t*)&As[s][row + gp][ks + tg * 2 + 8];
                    a[s][mi][3] = *(const uint32_t*)&As[s][row + gp + 8][ks + tg * 2 + 8];
                }
#pragma unroll
                for (int ni = 0; ni < 4; ni++) {
                    int col = wn + ni * 8;
                    bf[s][ni][0] = *(const uint32_t*)&Bs[s][col + gp][ks + tg * 2];
                    bf[s][ni][1] = *(const uint32_t*)&Bs[s][col + gp][ks + tg * 2 + 8];
                }
            }
#pragma unroll
            for (int mi = 0; mi < 2; mi++)
#pragma unroll
                for (int ni = 0; ni < 4; ni++) {
                    mma16816(d[mi][ni], a[0][mi], bf[0][ni]);  // hi*hi
                    mma16816(d[mi][ni], a[0][mi], bf[1][ni]);  // hi*lo
                    mma16816(d[mi][ni], a[1][mi], bf[0][ni]);  // lo*hi
                }
        }
    }

    // epilogue: + bias, fp32 store
#pragma unroll
    for (int mi = 0; mi < 2; mi++)
#pragma unroll
        for (int ni = 0; ni < 4; ni++) {
            int r = m0 + wm + mi * 16 + gp;
            int c = n0 + wn + ni * 8 + tg * 2;
            float b0 = bias[c], b1 = bias[c + 1];
            float* Cp = C + (size_t)r * N + c;
            float2 v0 = make_float2(d[mi][ni][0] + b0, d[mi][ni][1] + b1);
            float2 v1 = make_float2(d[mi][ni][2] + b0, d[mi][ni][3] + b1);
            *(float2*)(Cp) = v0;
            *(float2*)(Cp + 8 * N) = v1;
        }
}

// ---------------------------------------------------------------------------
// K3: fused scores(tanh) + softmax + context.
// Grid: 128 blocks = (b, 8-query tile). 512 threads.
// ---------------------------------------------------------------------------
#define QT 8
#define VT 64
#define HP (HH + 4)   // padded row stride (floats) for conflict-free LDS.128
#define VP (VV + 8)

// dynamic smem layout (floats):
//   qp_s   [QT][HP]      4128
//   buf    [VT][HP]     33024   (vp tiles, later values tiles)
//   wc_s   [HH]           512
//   sc     [QT][VP]      4160   (exp-scores, later weights)
//   wsum   [16]
//   mask_s [VV] (ints)    512
#define SMEM_FLOATS (QT*HP + VT*HP + HH + QT*VP + 16 + VV)
#define SMEM_BYTES (SMEM_FLOATS * 4)

__global__ __launch_bounds__(512, 1) void attn_kernel(
    const float* __restrict__ qp, const float* __restrict__ vp,
    const float* __restrict__ values, const int* __restrict__ mask,
    const float* __restrict__ wc, const float* __restrict__ bc,
    float* __restrict__ out_ctx, float* __restrict__ out_w) {
    extern __shared__ float sm[];
    float* qp_s = sm;
    float* buf = qp_s + QT * HP;
    float* wc_s = buf + VT * HP;
    float* sc = wc_s + HH;
    float* wsum = sc + QT * VP;
    int* mask_s = (int*)(wsum + 16);

    const int tid = threadIdx.x;
    const int b = blockIdx.x >> 4;
    const int qt = blockIdx.x & 15;
    const int q0 = qt * QT;

    // load qp tile, wc, mask
    for (int i = tid; i < QT * (HH / 4); i += 512) {
        int r = i / (HH / 4), c = i % (HH / 4);
        ((float4*)(qp_s + r * HP))[c] =
            ((const float4*)(qp + (size_t)(b * QQ + q0 + r) * HH))[c];
    }
    for (int i = tid; i < HH; i += 512) wc_s[i] = wc[i];
    for (int i = tid; i < VV; i += 512) mask_s[i] = mask[b * VV + i];
    const float bcv = bc[0];

    const int q = tid >> 6;    // 0..7
    const int vl = tid & 63;   // 0..63

    // ---- score phase: sc[q][v] = exp(score) (unnormalized), 0 if masked ----
    for (int vt = 0; vt < VV; vt += VT) {
        __syncthreads();
        for (int i = tid; i < VT * (HH / 4); i += 512) {
            int r = i / (HH / 4), c = i % (HH / 4);
            ((float4*)(buf + r * HP))[c] =
                ((const float4*)(vp + (size_t)(b * VV + vt + r) * HH))[c];
        }
        __syncthreads();

        const float4* qrow = (const float4*)(qp_s + q * HP);
        const float4* vrow = (const float4*)(buf + vl * HP);
        const float4* wrow = (const float4*)wc_s;
        float acc = 0.0f;
#pragma unroll 4
        for (int h4 = 0; h4 < HH / 4; h4++) {
            float4 a = qrow[h4];
            float4 c = vrow[h4];
            float4 w = wrow[h4];
            acc = fmaf(w.x, tanh_acc(a.x + c.x), acc);
            acc = fmaf(w.y, tanh_acc(a.y + c.y), acc);
            acc = fmaf(w.z, tanh_acc(a.z + c.z), acc);
            acc = fmaf(w.w, tanh_acc(a.w + c.w), acc);
        }
        acc += bcv;
        int v = vt + vl;
        // |score| <= ~18 -> exp never overflows; masked -> exactly 0 (matches exp(-inf))
        float p = mask_s[v] ? fast_ex2(acc * 1.4426950408889634f) : 0.0f;
        sc[q * VP + v] = p;
    }
    __syncthreads();

    // ---- deterministic row sums (shuffle + per-warp partials) ----
    {
        float s = 0.0f;
#pragma unroll
        for (int j = 0; j < 8; j++) s += sc[q * VP + vl + 64 * j];
#pragma unroll
        for (int off = 16; off; off >>= 1) s += __shfl_down_sync(0xffffffffu, s, off);
        if ((tid & 31) == 0) wsum[tid >> 5] = s;
    }
    __syncthreads();
    const float inv = 1.0f / (wsum[2 * q] + wsum[2 * q + 1]);

    // normalize in smem + write weights output
    {
        float* outw_row = out_w + (size_t)(b * QQ + q0 + q) * VV;
#pragma unroll
        for (int j = 0; j < 8; j++) {
            int v = vl + 64 * j;
            float w = sc[q * VP + v] * inv;
            sc[q * VP + v] = w;
            outw_row[v] = w;
        }
    }

    // ---- context phase: ctx[q][h] = sum_v w[q][v] * values[b][v][h] ----
    const int hq = tid & 127;  // float4 column index 0..127
    const int qg = tid >> 7;   // 0..3 -> query pair (2qg, 2qg+1)
    float4 acc0 = make_float4(0.f, 0.f, 0.f, 0.f);
    float4 acc1 = make_float4(0.f, 0.f, 0.f, 0.f);

    for (int vt = 0; vt < VV; vt += VT) {
        __syncthreads();
        for (int i = tid; i < VT * (HH / 4); i += 512) {
            int r = i / (HH / 4), c = i % (HH / 4);
            ((float4*)(buf + r * HP))[c] =
                ((const float4*)(values + (size_t)(b * VV + vt + r) * HH))[c];
        }
        __syncthreads();

        const float* w0 = sc + (2 * qg) * VP + vt;
        const float* w1 = sc + (2 * qg + 1) * VP + vt;
#pragma unroll 4
        for (int v = 0; v < VT; v += 2) {
            float2 a0 = *(const float2*)(w0 + v);
            float2 a1 = *(const float2*)(w1 + v);
            float4 c0 = ((const float4*)(buf + v * HP))[hq];
            float4 c1 = ((const float4*)(buf + (v + 1) * HP))[hq];
            acc0.x += a0.x * c0.x + a0.y * c1.x;
            acc0.y += a0.x * c0.y + a0.y * c1.y;
            acc0.z += a0.x * c0.z + a0.y * c1.z;
            acc0.w += a0.x * c0.w + a0.y * c1.w;
            acc1.x += a1.x * c0.x + a1.y * c1.x;
            acc1.y += a1.x * c0.y + a1.y * c1.y;
            acc1.z += a1.x * c0.z + a1.y * c1.z;
            acc1.w += a1.x * c0.w + a1.y * c1.w;
        }
    }
    float* oc0 = out_ctx + (size_t)(b * QQ + q0 + 2 * qg) * HH;
    ((float4*)oc0)[hq] = acc0;
    ((float4*)(oc0 + HH))[hq] = acc1;
}

// ---------------------------------------------------------------------------
// Launch
// ---------------------------------------------------------------------------
extern "C" void kernel_launch(void* const* d_in, const int* in_sizes, int n_in,
                              void* d_out, int out_size) {
    const float* query  = (const float*)d_in[0];
    const float* values = (const float*)d_in[1];
    const int*   mask   = (const int*)d_in[2];
    const float* Wq     = (const float*)d_in[3];
    const float* bq     = (const float*)d_in[4];
    const float* Wv     = (const float*)d_in[5];
    const float* bv     = (const float*)d_in[6];
    const float* wc     = (const float*)d_in[7];
    const float* bc     = (const float*)d_in[8];

    float* out_ctx = (float*)d_out;
    float* out_w   = (float*)d_out + (size_t)BB * QQ * HH;

    void *qhi, *qlo, *vhi, *vlo, *wqhi, *wqlo, *wvhi, *wvlo, *qp, *vp;
    cudaGetSymbolAddress(&qhi, g_qhi);
    cudaGetSymbolAddress(&qlo, g_qlo);
    cudaGetSymbolAddress(&vhi, g_vhi);
    cudaGetSymbolAddress(&vlo, g_vlo);
    cudaGetSymbolAddress(&wqhi, g_wqhi);
    cudaGetSymbolAddress(&wqlo, g_wqlo);
    cudaGetSymbolAddress(&wvhi, g_wvhi);
    cudaGetSymbolAddress(&wvlo, g_wvlo);
    cudaGetSymbolAddress(&qp, g_qp);
    cudaGetSymbolAddress(&vp, g_vp);

    // K1: bf16 hi/lo splits
    convert_split_kernel<<<(BB*QQ*HH)/256, 256>>>(query, (__nv_bfloat16*)qhi, (__nv_bfloat16*)qlo, BB*QQ*HH);
    convert_split_kernel<<<(BB*VV*HH)/256, 256>>>(values, (__nv_bfloat16*)vhi, (__nv_bfloat16*)vlo, BB*VV*HH);
    convert_split_kernel<<<(HH*HH)/256, 256>>>(Wq, (__nv_bfloat16*)wqhi, (__nv_bfloat16*)wqlo, HH*HH);
    convert_split_kernel<<<(HH*HH)/256, 256>>>(Wv, (__nv_bfloat16*)wvhi, (__nv_bfloat16*)wvlo, HH*HH);

    // K2: projections (3x-split bf16 tensor GEMM, fp32 accuracy)
    dim3 gq(BB * QQ / GBM, HH / GBN);   // (8, 8)
    dim3 gv(BB * VV / GBM, HH / GBN);   // (32, 8)
    gemm_nt_split_kernel<<<gq, 256>>>((__nv_bfloat16*)qhi, (__nv_bfloat16*)qlo,
                                      (__nv_bfloat16*)wqhi, (__nv_bfloat16*)wqlo,
                                      bq, (float*)qp);
    gemm_nt_split_kernel<<<gv, 256>>>((__nv_bfloat16*)vhi, (__nv_bfloat16*)vlo,
                                      (__nv_bfloat16*)wvhi, (__nv_bfloat16*)wvlo,
                                      bv, (float*)vp);

    // K3: fused tanh-scores + softmax + context
    cudaFuncSetAttribute(attn_kernel, cudaFuncAttributeMaxDynamicSharedMemorySize, SMEM_BYTES);
    attn_kernel<<<BB * (QQ / QT), 512, SMEM_BYTES>>>(
        (const float*)qp, (const float*)vp, values, mask, wc, bc, out_ctx, out_w);
}

// round 2
// speedup vs baseline: 1.2009x; 1.2009x over previous
#include <cuda_runtime.h>
#include <cuda_bf16.h>
#include <cstdint>

// ---------------------------------------------------------------------------
// Problem sizes (fixed)
// ---------------------------------------------------------------------------
#define BB 8
#define QQ 128
#define VV 512
#define HH 512

#define NQ (BB*QQ*HH)   // 524288
#define NV (BB*VV*HH)   // 2097152
#define NW (HH*HH)      // 262144

// ---------------------------------------------------------------------------
// Device scratch (no allocations allowed)
// ---------------------------------------------------------------------------
__device__ __nv_bfloat16 g_qhi[NQ], g_qlo[NQ];
__device__ __nv_bfloat16 g_vhi[NV], g_vlo[NV];
__device__ __nv_bfloat16 g_wqhi[NW], g_wqlo[NW];
__device__ __nv_bfloat16 g_wvhi[NW], g_wvlo[NW];
__device__ float g_qp[NQ];
__device__ float g_vp[NV];

// ---------------------------------------------------------------------------
// Fast transcendentals (always MUFU, regardless of compile flags)
// ---------------------------------------------------------------------------
__device__ __forceinline__ float fast_ex2(float x) {
    float y;
    asm("ex2.approx.ftz.f32 %0, %1;" : "=f"(y) : "f"(x));
    return y;
}
// single-MUFU tanh (sm_75+), max abs err ~4.9e-4
__device__ __forceinline__ float tanh_fast(float x) {
    float y;
    asm("tanh.approx.f32 %0, %1;" : "=f"(y) : "f"(x));
    return y;
}

// ---------------------------------------------------------------------------
// K1: fused split fp32 -> bf16 hi + bf16 lo for all four tensors
// ---------------------------------------------------------------------------
__global__ void convert_all_kernel(const float* __restrict__ query,
                                   const float* __restrict__ values,
                                   const float* __restrict__ Wq,
                                   const float* __restrict__ Wv,
                                   __nv_bfloat16* __restrict__ qhi, __nv_bfloat16* __restrict__ qlo,
                                   __nv_bfloat16* __restrict__ vhi, __nv_bfloat16* __restrict__ vlo,
                                   __nv_bfloat16* __restrict__ wqhi, __nv_bfloat16* __restrict__ wqlo,
                                   __nv_bfloat16* __restrict__ wvhi, __nv_bfloat16* __restrict__ wvlo) {
    int i = blockIdx.x * blockDim.x + threadIdx.x;
    const float* src;
    __nv_bfloat16 *hi, *lo;
    int j = i;
    if (j < NQ)                    { src = query;  hi = qhi;  lo = qlo;  }
    else if ((j -= NQ) < NV)       { src = values; hi = vhi;  lo = vlo;  }
    else if ((j -= NV) < NW)       { src = Wq;     hi = wqhi; lo = wqlo; }
    else if ((j -= NW) < NW)       { src = Wv;     hi = wvhi; lo = wvlo; }
    else return;
    float x = src[j];
    __nv_bfloat16 h = __float2bfloat16(x);
    hi[j] = h;
    lo[j] = __float2bfloat16(x - __bfloat162float(h));
}

// ---------------------------------------------------------------------------
// K2: C[m][n] = sum_k A[m][k]*B[n][k] + bias[n]   (NT GEMM, 3x bf16 split)
// Block tile 128x64, BK=32, 8 warps (4x2), warp tile 32x32 via m16n8k16.
// ---------------------------------------------------------------------------
#define GBM 128
#define GBN 64
#define GBK 32

__device__ __forceinline__ void mma16816(float* d, const uint32_t* a, const uint32_t* b) {
    asm volatile(
        "mma.sync.aligned.m16n8k16.row.col.f32.bf16.bf16.f32 "
        "{%0,%1,%2,%3}, {%4,%5,%6,%7}, {%8,%9}, {%0,%1,%2,%3};"
        : "+f"(d[0]), "+f"(d[1]), "+f"(d[2]), "+f"(d[3])
        : "r"(a[0]), "r"(a[1]), "r"(a[2]), "r"(a[3]), "r"(b[0]), "r"(b[1]));
}

__global__ __launch_bounds__(256) void gemm_nt_split_kernel(
    const __nv_bfloat16* __restrict__ Ahi, const __nv_bfloat16* __restrict__ Alo,
    const __nv_bfloat16* __restrict__ Bhi, const __nv_bfloat16* __restrict__ Blo,
    const float* __restrict__ bias, float* __restrict__ C) {
    const int K = HH;  // 512
    const int N = HH;  // 512
    __shared__ __align__(16) __nv_bfloat16 As[2][GBM][GBK + 8];
    __shared__ __align__(16) __nv_bfloat16 Bs[2][GBN][GBK + 8];

    const int m0 = blockIdx.x * GBM;
    const int n0 = blockIdx.y * GBN;
    const int tid = threadIdx.x;
    const int wid = tid >> 5;
    const int lane = tid & 31;
    const int wm = (wid >> 1) * 32;  // warp m offset in block tile
    const int wn = (wid & 1) * 32;   // warp n offset
    const int gp = lane >> 2;
    const int tg = lane & 3;

    float d[2][4][4];
#pragma unroll
    for (int mi = 0; mi < 2; mi++)
#pragma unroll
        for (int ni = 0; ni < 4; ni++)
#pragma unroll
            for (int r = 0; r < 4; r++) d[mi][ni][r] = 0.0f;

    for (int k0 = 0; k0 < K; k0 += GBK) {
        __syncthreads();
        // stage A (128x32) hi+lo and B (64x32) hi+lo
#pragma unroll
        for (int s = 0; s < 2; s++) {
            const __nv_bfloat16* srcA = s ? Alo : Ahi;
#pragma unroll
            for (int i = 0; i < 2; i++) {
                int linear = i * 256 + tid;
                int r = linear >> 2;
                int c = (linear & 3) * 8;
                uint4 v = *(const uint4*)(srcA + (size_t)(m0 + r) * K + k0 + c);
                *(uint4*)(&As[s][r][c]) = v;
            }
            const __nv_bfloat16* srcB = s ? Blo : Bhi;
            {
                int r = tid >> 2;
                int c = (tid & 3) * 8;
                uint4 v = *(const uint4*)(srcB + (size_t)(n0 + r) * K + k0 + c);
                *(uint4*)(&Bs[s][r][c]) = v;
            }
        }
        __syncthreads();

#pragma unroll
        for (int ks = 0; ks < GBK; ks += 16) {
            uint32_t a[2][2][4];
            uint32_t bf[2][4][2];
#pragma unroll
            for (int s = 0; s < 2; s++) {
#pragma unroll
                for (int mi = 0; mi < 2; mi++) {
                    int row = wm + mi * 16;
                    a[s][mi][0] = *(const uint32_t*)&As[s][row + gp][ks + tg * 2];
                    a[s][mi][1] = *(const uint32_t*)&As[s][row + gp + 8][ks + tg * 2];
                    a[s][mi][2] = *(const uint32_t*)&As[s][row + gp][ks + tg * 2 + 8];
                    a[s][mi][3] = *(const uint32_t*)&As[s][row + gp + 8][ks + tg * 2 + 8];
                }
#pragma unroll
                for (int ni = 0; ni < 4; ni++) {
                    int col = wn + ni * 8;
                    bf[s][ni][0] = *(const uint32_t*)&Bs[s][col + gp][ks + tg * 2];
                    bf[s][ni][1] = *(const uint32_t*)&Bs[s][col + gp][ks + tg * 2 + 8];
                }
            }
#pragma unroll
            for (int mi = 0; mi < 2; mi++)
#pragma unroll
                for (int ni = 0; ni < 4; ni++) {
                    mma16816(d[mi][ni], a[0][mi], bf[0][ni]);  // hi*hi
                    mma16816(d[mi][ni], a[0][mi], bf[1][ni]);  // hi*lo
                    mma16816(d[mi][ni], a[1][mi], bf[0][ni]);  // lo*hi
                }
        }
    }

    // epilogue: + bias, fp32 store
#pragma unroll
    for (int mi = 0; mi < 2; mi++)
#pragma unroll
        for (int ni = 0; ni < 4; ni++) {
            int r = m0 + wm + mi * 16 + gp;
            int c = n0 + wn + ni * 8 + tg * 2;
            float b0 = bias[c], b1 = bias[c + 1];
            float* Cp = C + (size_t)r * N + c;
            float2 v0 = make_float2(d[mi][ni][0] + b0, d[mi][ni][1] + b1);
            float2 v1 = make_float2(d[mi][ni][2] + b0, d[mi][ni][3] + b1);
            *(float2*)(Cp) = v0;
            *(float2*)(Cp + 8 * N) = v1;
        }
}

// ---------------------------------------------------------------------------
// K3: fused scores(tanh) + softmax + context.
// Grid: 128 blocks = (b, 8-query tile). 512 threads.
// Score phase thread mapping: q = tid>>6 (8), vg = (tid>>2)&15 (16 groups of
// 4 v-rows), hc = tid&3 (interleaved h-chunks, h4 == hc mod 4).
// 4 v-rows per thread amortizes q/wc LDS traffic (12 B/elem -> 6 B/elem);
// interleaved hc keeps LDS.128 conflict-free. Partials reduced via
// xor-butterfly over the 4 hc lanes (deterministic).
// ---------------------------------------------------------------------------
#define QT 8
#define VT 64
#define HP (HH + 4)   // padded row stride (floats)
#define VP (VV + 8)

#define SMEM_FLOATS (QT*HP + VT*HP + HH + QT*VP + 16 + VV)
#define SMEM_BYTES (SMEM_FLOATS * 4)

__global__ __launch_bounds__(512, 1) void attn_kernel(
    const float* __restrict__ qp, const float* __restrict__ vp,
    const float* __restrict__ values, const int* __restrict__ mask,
    const float* __restrict__ wc, const float* __restrict__ bc,
    float* __restrict__ out_ctx, float* __restrict__ out_w) {
    extern __shared__ float sm[];
    float* qp_s = sm;
    float* buf = qp_s + QT * HP;
    float* wc_s = buf + VT * HP;
    float* sc = wc_s + HH;
    float* wsum = sc + QT * VP;
    int* mask_s = (int*)(wsum + 16);

    const int tid = threadIdx.x;
    const int b = blockIdx.x >> 4;
    const int qt = blockIdx.x & 15;
    const int q0 = qt * QT;

    // load qp tile, wc, mask
    for (int i = tid; i < QT * (HH / 4); i += 512) {
        int r = i / (HH / 4), c = i % (HH / 4);
        ((float4*)(qp_s + r * HP))[c] =
            ((const float4*)(qp + (size_t)(b * QQ + q0 + r) * HH))[c];
    }
    for (int i = tid; i < HH; i += 512) wc_s[i] = wc[i];
    for (int i = tid; i < VV; i += 512) mask_s[i] = mask[b * VV + i];
    const float bcv = bc[0];

    const int hc = tid & 3;         // h-chunk (interleaved)
    const int vg = (tid >> 2) & 15; // v group of 4 rows
    const int q = tid >> 6;         // 0..7

    // ---- score phase: sc[q][v] = exp(score) (unnormalized), 0 if masked ----
    for (int vt = 0; vt < VV; vt += VT) {
        __syncthreads();
        for (int i = tid; i < VT * (HH / 4); i += 512) {
            int r = i / (HH / 4), c = i % (HH / 4);
            ((float4*)(buf + r * HP))[c] =
                ((const float4*)(vp + (size_t)(b * VV + vt + r) * HH))[c];
        }
        __syncthreads();

        const float* qrow = qp_s + q * HP;
        const float* v0p = buf + (vg * 4 + 0) * HP;
        const float* v1p = buf + (vg * 4 + 1) * HP;
        const float* v2p = buf + (vg * 4 + 2) * HP;
        const float* v3p = buf + (vg * 4 + 3) * HP;
        float acc0 = 0.f, acc1 = 0.f, acc2 = 0.f, acc3 = 0.f;
#pragma unroll 8
        for (int i = 0; i < 32; i++) {
            int h = i * 16 + hc * 4;      // thread hc handles h4 == hc (mod 4)
            float4 a = *(const float4*)(qrow + h);
            float4 w = *(const float4*)(wc_s + h);
            float4 c0 = *(const float4*)(v0p + h);
            float4 c1 = *(const float4*)(v1p + h);
            float4 c2 = *(const float4*)(v2p + h);
            float4 c3 = *(const float4*)(v3p + h);
            acc0 = fmaf(w.x, tanh_fast(a.x + c0.x), acc0);
            acc0 = fmaf(w.y, tanh_fast(a.y + c0.y), acc0);
            acc0 = fmaf(w.z, tanh_fast(a.z + c0.z), acc0);
            acc0 = fmaf(w.w, tanh_fast(a.w + c0.w), acc0);
            acc1 = fmaf(w.x, tanh_fast(a.x + c1.x), acc1);
            acc1 = fmaf(w.y, tanh_fast(a.y + c1.y), acc1);
            acc1 = fmaf(w.z, tanh_fast(a.z + c1.z), acc1);
            acc1 = fmaf(w.w, tanh_fast(a.w + c1.w), acc1);
            acc2 = fmaf(w.x, tanh_fast(a.x + c2.x), acc2);
            acc2 = fmaf(w.y, tanh_fast(a.y + c2.y), acc2);
            acc2 = fmaf(w.z, tanh_fast(a.z + c2.z), acc2);
            acc2 = fmaf(w.w, tanh_fast(a.w + c2.w), acc2);
            acc3 = fmaf(w.x, tanh_fast(a.x + c3.x), acc3);
            acc3 = fmaf(w.y, tanh_fast(a.y + c3.y), acc3);
            acc3 = fmaf(w.z, tanh_fast(a.z + c3.z), acc3);
            acc3 = fmaf(w.w, tanh_fast(a.w + c3.w), acc3);
        }
        // butterfly-reduce the 4 h-chunks (lanes differing in bits 0-1)
        acc0 += __shfl_xor_sync(0xffffffffu, acc0, 1);
        acc0 += __shfl_xor_sync(0xffffffffu, acc0, 2);
        acc1 += __shfl_xor_sync(0xffffffffu, acc1, 1);
        acc1 += __shfl_xor_sync(0xffffffffu, acc1, 2);
        acc2 += __shfl_xor_sync(0xffffffffu, acc2, 1);
        acc2 += __shfl_xor_sync(0xffffffffu, acc2, 2);
        acc3 += __shfl_xor_sync(0xffffffffu, acc3, 1);
        acc3 += __shfl_xor_sync(0xffffffffu, acc3, 2);
        // lane hc writes v-row vg*4 + hc
        float myacc = (hc == 0) ? acc0 : (hc == 1) ? acc1 : (hc == 2) ? acc2 : acc3;
        int v = vt + vg * 4 + hc;
        float p = mask_s[v] ? fast_ex2((myacc + bcv) * 1.4426950408889634f) : 0.0f;
        sc[q * VP + v] = p;
    }
    __syncthreads();

    // ---- deterministic row sums (shuffle + per-warp partials) ----
    const int vl = tid & 63;
    {
        float s = 0.0f;
#pragma unroll
        for (int j = 0; j < 8; j++) s += sc[q * VP + vl + 64 * j];
#pragma unroll
        for (int off = 16; off; off >>= 1) s += __shfl_down_sync(0xffffffffu, s, off);
        if ((tid & 31) == 0) wsum[tid >> 5] = s;
    }
    __syncthreads();
    const float inv = 1.0f / (wsum[2 * q] + wsum[2 * q + 1]);

    // normalize in smem + write weights output
    {
        float* outw_row = out_w + (size_t)(b * QQ + q0 + q) * VV;
#pragma unroll
        for (int j = 0; j < 8; j++) {
            int v = vl + 64 * j;
            float w = sc[q * VP + v] * inv;
            sc[q * VP + v] = w;
            outw_row[v] = w;
        }
    }

    // ---- context phase: ctx[q][h] = sum_v w[q][v] * values[b][v][h] ----
    const int hq = tid & 127;  // float4 column index 0..127
    const int qg = tid >> 7;   // 0..3 -> query pair (2qg, 2qg+1)
    float4 acc0 = make_float4(0.f, 0.f, 0.f, 0.f);
    float4 acc1 = make_float4(0.f, 0.f, 0.f, 0.f);

    for (int vt = 0; vt < VV; vt += VT) {
        __syncthreads();
        for (int i = tid; i < VT * (HH / 4); i += 512) {
            int r = i / (HH / 4), c = i % (HH / 4);
            ((float4*)(buf + r * HP))[c] =
                ((const float4*)(values + (size_t)(b * VV + vt + r) * HH))[c];
        }
        __syncthreads();

        const float* w0 = sc + (2 * qg) * VP + vt;
        const float* w1 = sc + (2 * qg + 1) * VP + vt;
#pragma unroll 4
        for (int v = 0; v < VT; v += 2) {
            float2 a0 = *(const float2*)(w0 + v);
            float2 a1 = *(const float2*)(w1 + v);
            float4 c0 = ((const float4*)(buf + v * HP))[hq];
            float4 c1 = ((const float4*)(buf + (v + 1) * HP))[hq];
            acc0.x += a0.x * c0.x + a0.y * c1.x;
            acc0.y += a0.x * c0.y + a0.y * c1.y;
            acc0.z += a0.x * c0.z + a0.y * c1.z;
            acc0.w += a0.x * c0.w + a0.y * c1.w;
            acc1.x += a1.x * c0.x + a1.y * c1.x;
            acc1.y += a1.x * c0.y + a1.y * c1.y;
            acc1.z += a1.x * c0.z + a1.y * c1.z;
            acc1.w += a1.x * c0.w + a1.y * c1.w;
        }
    }
    float* oc0 = out_ctx + (size_t)(b * QQ + q0 + 2 * qg) * HH;
    ((float4*)oc0)[hq] = acc0;
    ((float4*)(oc0 + HH))[hq] = acc1;
}

// ---------------------------------------------------------------------------
// Launch
// ---------------------------------------------------------------------------
extern "C" void kernel_launch(void* const* d_in, const int* in_sizes, int n_in,
                              void* d_out, int out_size) {
    const float* query  = (const float*)d_in[0];
    const float* values = (const float*)d_in[1];
    const int*   mask   = (const int*)d_in[2];
    const float* Wq     = (const float*)d_in[3];
    const float* bq     = (const float*)d_in[4];
    const float* Wv     = (const float*)d_in[5];
    const float* bv     = (const float*)d_in[6];
    const float* wc     = (const float*)d_in[7];
    const float* bc     = (const float*)d_in[8];

    float* out_ctx = (float*)d_out;
    float* out_w   = (float*)d_out + (size_t)BB * QQ * HH;

    void *qhi, *qlo, *vhi, *vlo, *wqhi, *wqlo, *wvhi, *wvlo, *qp, *vp;
    cudaGetSymbolAddress(&qhi, g_qhi);
    cudaGetSymbolAddress(&qlo, g_qlo);
    cudaGetSymbolAddress(&vhi, g_vhi);
    cudaGetSymbolAddress(&vlo, g_vlo);
    cudaGetSymbolAddress(&wqhi, g_wqhi);
    cudaGetSymbolAddress(&wqlo, g_wqlo);
    cudaGetSymbolAddress(&wvhi, g_wvhi);
    cudaGetSymbolAddress(&wvlo, g_wvlo);
    cudaGetSymbolAddress(&qp, g_qp);
    cudaGetSymbolAddress(&vp, g_vp);

    // K1: fused bf16 hi/lo split (one launch for all four tensors)
    const int ntot = NQ + NV + 2 * NW;
    convert_all_kernel<<<(ntot + 255) / 256, 256>>>(
        query, values, Wq, Wv,
        (__nv_bfloat16*)qhi, (__nv_bfloat16*)qlo,
        (__nv_bfloat16*)vhi, (__nv_bfloat16*)vlo,
        (__nv_bfloat16*)wqhi, (__nv_bfloat16*)wqlo,
        (__nv_bfloat16*)wvhi, (__nv_bfloat16*)wvlo);

    // K2: projections (3x-split bf16 tensor GEMM, fp32 accuracy)
    dim3 gq(BB * QQ / GBM, HH / GBN);   // (8, 8)
    dim3 gv(BB * VV / GBM, HH / GBN);   // (32, 8)
    gemm_nt_split_kernel<<<gq, 256>>>((__nv_bfloat16*)qhi, (__nv_bfloat16*)qlo,
                                      (__nv_bfloat16*)wqhi, (__nv_bfloat16*)wqlo,
                                      bq, (float*)qp);
    gemm_nt_split_kernel<<<gv, 256>>>((__nv_bfloat16*)vhi, (__nv_bfloat16*)vlo,
                                      (__nv_bfloat16*)wvhi, (__nv_bfloat16*)wvlo,
                                      bv, (float*)vp);

    // K3: fused tanh-scores + softmax + context
    cudaFuncSetAttribute(attn_kernel, cudaFuncAttributeMaxDynamicSharedMemorySize, SMEM_BYTES);
    attn_kernel<<<BB * (QQ / QT), 512, SMEM_BYTES>>>(
        (const float*)qp, (const float*)vp, values, mask, wc, bc, out_ctx, out_w);
}